// round 16
// baseline (speedup 1.0000x reference)
#include <cuda_runtime.h>
#include <cuda_bf16.h>
#include <cstdint>

#define DIM   128
#define HEADS 8
#define MAXD  12
#define NTOK  256
#define MSZ   (DIM*DIM)      // 16384
#define NMAT  16             // sos (prims[-1]) unused by reference output
#define NPID  126            // prefix products of length 1..6: 2+4+...+64

// ---------------- device scratch ----------------
// prefix products indexed pid = 2^L - 2 + b (b = MSB-first digit string)
__device__ __align__(16) float         g_prod_f [NPID*HEADS*MSZ];   // 66 MB
__device__ __align__(16) __nv_bfloat16 g_prod_h [NPID*HEADS*MSZ];   // 33 MB
__device__ __align__(16) __nv_bfloat16 g_prod_l [NPID*HEADS*MSZ];   // 33 MB

// ---------------- helpers ----------------
__device__ __forceinline__ uint32_t smem_u32(const void* p) {
    uint32_t a;
    asm("{ .reg .u64 t; cvta.to.shared.u64 t, %1; cvt.u32.u64 %0, t; }" : "=r"(a) : "l"(p));
    return a;
}
#define STS128Q(a, r0, r1, r2, r3) \
    asm volatile("st.shared.v4.b32 [%0], {%1, %2, %3, %4};" \
                 :: "r"(a), "r"(r0), "r"(r1), "r"(r2), "r"(r3) : "memory")
#define STS32(a, v) \
    asm volatile("st.shared.b32 [%0], %1;" :: "r"(a), "r"(v) : "memory")
#define STS16(a, v) \
    asm volatile("st.shared.b16 [%0], %1;" :: "r"(a), "h"(v) : "memory")
#define LDS32(v, a) \
    asm volatile("ld.shared.b32 %0, [%1];" : "=r"(v) : "r"(a))
#define LDSM4(r0, r1, r2, r3, addr) \
    asm volatile("ldmatrix.sync.aligned.m8n8.x4.shared.b16 {%0, %1, %2, %3}, [%4];" \
                 : "=r"(r0), "=r"(r1), "=r"(r2), "=r"(r3) : "r"(addr))
#define LDSM4T(r0, r1, r2, r3, addr) \
    asm volatile("ldmatrix.sync.aligned.m8n8.x4.trans.shared.b16 {%0, %1, %2, %3}, [%4];" \
                 : "=r"(r0), "=r"(r1), "=r"(r2), "=r"(r3) : "r"(addr))
#define MMA16816(d, a, b0, b1) \
    asm volatile("mma.sync.aligned.m16n8k16.row.col.f32.bf16.bf16.f32 " \
                 "{%0, %1, %2, %3}, {%4, %5, %6, %7}, {%8, %9}, {%0, %1, %2, %3};" \
                 : "+f"((d)[0]), "+f"((d)[1]), "+f"((d)[2]), "+f"((d)[3]) \
                 : "r"((a)[0]), "r"((a)[1]), "r"((a)[2]), "r"((a)[3]), \
                   "r"(b0), "r"(b1))
__device__ __forceinline__ uint32_t pack_bf2(float flo, float fhi) {
    uint32_t r;
    asm("cvt.rn.bf16x2.f32 %0, %1, %2;" : "=r"(r) : "f"(fhi), "f"(flo));
    return r;
}

// padded rows: 136 bf16 = 272 B; tile = 128*272 B
#define RSB     272
#define TILE_B  34816
#define SMEM_EXPM (6*TILE_B)     // 208896 B
#define SMEM_LVL  (4*TILE_B)     // 139264 B (P0 hi/lo + P1 hi/lo)
#define SMEM_GEMM (2*TILE_B)     // 69632 B  (B tile hi/lo)

__device__ __forceinline__ void load_pad(uint32_t dst, const __nv_bfloat16* g,
                                         int t, int T) {
    const uint4* g4 = (const uint4*)g;
    for (int q = t; q < 2048; q += T) {
        uint4 v = g4[q];
        int r = q >> 4, c = (q & 15) << 3;
        STS128Q(dst + r * RSB + c * 2, v.x, v.y, v.z, v.w);
    }
}

// A fragments directly from global row-major bf16 (layout == LDSM4 delivery)
__device__ __forceinline__ void load_a_frags_g(
    const __nv_bfloat16* Ghi, const __nv_bfloat16* Glo,
    uint32_t Ah[8][4], uint32_t Al[8][4], int r0w, int g, int tig)
{
#pragma unroll
    for (int kk = 0; kk < 8; kk++) {
#pragma unroll
        for (int q = 0; q < 4; q++) {
            int row = r0w + g + ((q & 1) ? 8 : 0);
            int col = kk * 16 + tig * 2 + ((q & 2) ? 8 : 0);
            Ah[kk][q] = *(const uint32_t*)(Ghi + (size_t)row * DIM + col);
            Al[kk][q] = *(const uint32_t*)(Glo + (size_t)row * DIM + col);
        }
    }
}

// 3-pass bf16 HMMA: acc(16x[4]) = Arows(16) @ B(128x128); B row-major via
// ldmatrix.trans. bSlot = hi base; lo at +TILE_B.
__device__ __forceinline__ void gemm3(float acc[16][4],
                                      const uint32_t Ah[8][4],
                                      const uint32_t Al[8][4],
                                      uint32_t bSlot, uint32_t bT)
{
#pragma unroll
    for (int ni = 0; ni < 16; ni++)
#pragma unroll
        for (int q = 0; q < 4; q++) acc[ni][q] = 0.0f;
#pragma unroll
    for (int kk = 0; kk < 8; kk++) {
#pragma unroll
        for (int gq = 0; gq < 2; gq++) {
            uint32_t Bh[4][4], Bl[4][4];
#pragma unroll
            for (int j = 0; j < 4; j++) {
                uint32_t bA = bSlot + bT + (uint32_t)(kk * 16 * RSB)
                            + (uint32_t)((gq * 4 + j) * 32);
                LDSM4T(Bh[j][0], Bh[j][1], Bh[j][2], Bh[j][3], bA);
                LDSM4T(Bl[j][0], Bl[j][1], Bl[j][2], Bl[j][3], bA + TILE_B);
            }
#pragma unroll
            for (int j = 0; j < 4; j++) {
                int np = gq * 4 + j;
                MMA16816(acc[2*np],     Ah[kk], Bh[j][0], Bh[j][1]);
                MMA16816(acc[2*np + 1], Ah[kk], Bh[j][2], Bh[j][3]);
            }
#pragma unroll
            for (int j = 0; j < 4; j++) {
                int np = gq * 4 + j;
                MMA16816(acc[2*np],     Al[kk], Bh[j][0], Bh[j][1]);
                MMA16816(acc[2*np + 1], Al[kk], Bh[j][2], Bh[j][3]);
            }
#pragma unroll
            for (int j = 0; j < 4; j++) {
                int np = gq * 4 + j;
                MMA16816(acc[2*np],     Ah[kk], Bl[j][0], Bl[j][1]);
                MMA16816(acc[2*np + 1], Ah[kk], Bl[j][2], Bl[j][3]);
            }
        }
    }
}

__device__ __forceinline__ void conv_frags(const float acc[16][4],
                                           uint32_t Ah[8][4], uint32_t Al[8][4])
{
#pragma unroll
    for (int kk = 0; kk < 8; kk++) {
#pragma unroll
        for (int q = 0; q < 4; q++) {
            int nt = 2 * kk + (q >> 1);
            int bs = (q & 1) * 2;
            float v0 = acc[nt][bs], v1 = acc[nt][bs + 1];
            uint32_t hp = pack_bf2(v0, v1);
            float h0 = __uint_as_float(hp << 16);
            float h1 = __uint_as_float(hp & 0xffff0000u);
            Ah[kk][q] = hp;
            Al[kk][q] = pack_bf2(v0 - h0, v1 - h1);
        }
    }
}

// acc := cA*acc + cX*X + cI*I  (X from smem hi/lo)
__device__ __forceinline__ void epi_inplace(float acc[16][4],
    float cA, float cX, float cI, uint32_t xSlot, int r0w, int g, int tig)
{
    int r0 = r0w + g, r1 = r0w + g + 8;
#pragma unroll
    for (int ni = 0; ni < 16; ni++) {
        int col = ni * 8 + tig * 2;
        uint32_t a0 = xSlot + (uint32_t)(r0 * RSB + col * 2);
        uint32_t a1 = xSlot + (uint32_t)(r1 * RSB + col * 2);
        uint32_t h0, l0, h1, l1;
        LDS32(h0, a0); LDS32(l0, a0 + TILE_B);
        LDS32(h1, a1); LDS32(l1, a1 + TILE_B);
        float x00 = __uint_as_float(h0 << 16) + __uint_as_float(l0 << 16);
        float x01 = __uint_as_float(h0 & 0xffff0000u) + __uint_as_float(l0 & 0xffff0000u);
        float x10 = __uint_as_float(h1 << 16) + __uint_as_float(l1 << 16);
        float x11 = __uint_as_float(h1 & 0xffff0000u) + __uint_as_float(l1 & 0xffff0000u);
        acc[ni][0] = cA * acc[ni][0] + cX * x00 + ((r0 == col)     ? cI : 0.0f);
        acc[ni][1] = cA * acc[ni][1] + cX * x01 + ((r0 == col + 1) ? cI : 0.0f);
        acc[ni][2] = cA * acc[ni][2] + cX * x10 + ((r1 == col)     ? cI : 0.0f);
        acc[ni][3] = cA * acc[ni][3] + cX * x11 + ((r1 == col + 1) ? cI : 0.0f);
    }
}

__device__ __forceinline__ void store_buf(const float acc[16][4],
    uint32_t slot, int r0w, int g, int tig)
{
    int r0 = r0w + g, r1 = r0w + g + 8;
#pragma unroll
    for (int ni = 0; ni < 16; ni++) {
        int col = ni * 8 + tig * 2;
        float v0 = acc[ni][0], v1 = acc[ni][1];
        float v2 = acc[ni][2], v3 = acc[ni][3];
        uint32_t hp01 = pack_bf2(v0, v1), hp23 = pack_bf2(v2, v3);
        uint32_t lp01 = pack_bf2(v0 - __uint_as_float(hp01 << 16),
                                 v1 - __uint_as_float(hp01 & 0xffff0000u));
        uint32_t lp23 = pack_bf2(v2 - __uint_as_float(hp23 << 16),
                                 v3 - __uint_as_float(hp23 & 0xffff0000u));
        uint32_t a0 = slot + (uint32_t)(r0 * RSB + col * 2);
        uint32_t a1 = slot + (uint32_t)(r1 * RSB + col * 2);
        STS32(a0, hp01); STS32(a0 + TILE_B, lp01);
        STS32(a1, hp23); STS32(a1 + TILE_B, lp23);
    }
}

// write acc to f32 (optional) and bf16 hi/lo (optional) global row-major
__device__ __forceinline__ void write_acc(const float acc[16][4],
    float* outf, __nv_bfloat16* Gh, __nv_bfloat16* Gl, int r0w, int g, int tig)
{
    int r0 = r0w + g, r1 = r0w + g + 8;
#pragma unroll
    for (int ni = 0; ni < 16; ni++) {
        int col = ni * 8 + tig * 2;
        float v0 = acc[ni][0], v1 = acc[ni][1];
        float v2 = acc[ni][2], v3 = acc[ni][3];
        if (outf) {
            *(float2*)(outf + (size_t)r0 * DIM + col) = make_float2(v0, v1);
            *(float2*)(outf + (size_t)r1 * DIM + col) = make_float2(v2, v3);
        }
        if (Gh) {
            uint32_t hp01 = pack_bf2(v0, v1), hp23 = pack_bf2(v2, v3);
            uint32_t lp01 = pack_bf2(v0 - __uint_as_float(hp01 << 16),
                                     v1 - __uint_as_float(hp01 & 0xffff0000u));
            uint32_t lp23 = pack_bf2(v2 - __uint_as_float(hp23 << 16),
                                     v3 - __uint_as_float(hp23 & 0xffff0000u));
            *(uint32_t*)(Gh + (size_t)r0 * DIM + col) = hp01;
            *(uint32_t*)(Gh + (size_t)r1 * DIM + col) = hp23;
            *(uint32_t*)(Gl + (size_t)r0 * DIM + col) = lp01;
            *(uint32_t*)(Gl + (size_t)r1 * DIM + col) = lp23;
        }
    }
}

// ---------------- K1: steps via LCA, grid (256, 256 thr) ----------------
__global__ void k_steps(const int* __restrict__ positions,
                        float* __restrict__ steps_out)
{
    int i = blockIdx.x, j = threadIdx.x;
    int u = __ldg(positions + i), w = __ldg(positions + j);
    int du = 0, dw = 0;
    for (int x = u; x > 0; x = (x - 1) >> 1) du++;
    for (int x = w; x > 0; x = (x - 1) >> 1) dw++;
    int su = u, sw = w, a = du, b = dw;
    while (a > b) { su = (su - 1) >> 1; a--; }
    while (b > a) { sw = (sw - 1) >> 1; b--; }
    while (su != sw) { su = (su - 1) >> 1; sw = (sw - 1) >> 1; a--; }
    steps_out[i * NTOK + j] = (float)(du + dw - 2 * a);
}

// ---------------- K2: fused expm (one CTA per matrix) ----------------
// Writes pid 0/1 (length-1 products): offsets (digit*8+h)*MSZ == m*MSZ.
__global__ void __launch_bounds__(256) k_expm(const float* __restrict__ prim)
{
    extern __shared__ char smem[];
    uint32_t sb = smem_u32(smem);
    int tid = threadIdx.x, wid = tid >> 5, lane = tid & 31;
    int m = blockIdx.x;
    const float* A = prim + (size_t)m * MSZ;

    for (int e = tid; e < MSZ; e += 256) {
        int i = e >> 7, j = e & 127;
        float x = (A[e] - A[j * DIM + i]) * (1.0f / 16.0f);
        __nv_bfloat16 hb = __float2bfloat16(x);
        float hf = __bfloat162float(hb);
        __nv_bfloat16 lb = __float2bfloat16(x - hf);
        uint32_t ad = sb + (uint32_t)(i * RSB + j * 2);
        STS16(ad, (unsigned short)__bfloat16_as_ushort(hb));
        STS16(ad + TILE_B, (unsigned short)__bfloat16_as_ushort(lb));
    }
    __syncthreads();

    int r0w = wid * 16;
    int t   = lane >> 3, r8 = lane & 7;
    int g   = lane >> 2, tig = lane & 3;
    uint32_t aOff = (uint32_t)((r0w + (t & 1) * 8 + r8) * RSB + (t >> 1) * 16);
    uint32_t bT   = (uint32_t)(((t & 1) * 8 + r8) * RSB + (t >> 1) * 16);
    uint32_t slotX  = sb + 0 * TILE_B;
    uint32_t slotB0 = sb + 2 * TILE_B;
    uint32_t slotB1 = sb + 4 * TILE_B;

    const float c2 = 1.0f/2.0f, c3 = 1.0f/6.0f, c4 = 1.0f/24.0f, c5 = 1.0f/120.0f;
    const float c6 = 1.0f/720.0f, c7 = 1.0f/5040.0f, c8 = 1.0f/40320.0f;

    uint32_t Xa[8][4], Xal[8][4];
#pragma unroll
    for (int kk = 0; kk < 8; kk++) {
        LDSM4(Xa[kk][0], Xa[kk][1], Xa[kk][2], Xa[kk][3], slotX + aOff + kk * 32);
        LDSM4(Xal[kk][0], Xal[kk][1], Xal[kk][2], Xal[kk][3],
              slotX + TILE_B + aOff + kk * 32);
    }

    float acc[16][4];
    uint32_t X2h[8][4], X2l[8][4];

    gemm3(acc, Xa, Xal, slotX, bT);
    conv_frags(acc, X2h, X2l);
    epi_inplace(acc, c8, c7, c6, slotX, r0w, g, tig);
    store_buf(acc, slotB0, r0w, g, tig);
    __syncthreads();
    gemm3(acc, X2h, X2l, slotB0, bT);
    epi_inplace(acc, 1.0f, c5, c4, slotX, r0w, g, tig);
    store_buf(acc, slotB1, r0w, g, tig);
    __syncthreads();
    gemm3(acc, X2h, X2l, slotB1, bT);
    epi_inplace(acc, 1.0f, c3, c2, slotX, r0w, g, tig);
    store_buf(acc, slotB0, r0w, g, tig);
    __syncthreads();
    gemm3(acc, X2h, X2l, slotB0, bT);
    epi_inplace(acc, 1.0f, 1.0f, 1.0f, slotX, r0w, g, tig);
    store_buf(acc, slotB1, r0w, g, tig);
    uint32_t Sh[8][4], Sl[8][4];
    conv_frags(acc, Sh, Sl);
    __syncthreads();

#pragma unroll
    for (int q = 0; q < 4; q++) {
        uint32_t rd = (q & 1) ? slotB0 : slotB1;
        uint32_t wr = (q & 1) ? slotB1 : slotB0;
        gemm3(acc, Sh, Sl, rd, bT);
        conv_frags(acc, Sh, Sl);
        if (q < 3) {
            store_buf(acc, wr, r0w, g, tig);
            __syncthreads();
        }
    }

    write_acc(acc, g_prod_f + (size_t)m * MSZ,
              g_prod_h + (size_t)m * MSZ, g_prod_l + (size_t)m * MSZ,
              r0w, g, tig);
}

// ---------------- K3: build ALL prefix products in one launch -------------
// grid (64, HEADS): CTA s computes the chain P(s5)@P(s4)@...@P(s0) with
// register-chained GEMMs, writing prod(L, s>>(6-L)) when it is the canonical
// CTA for that prefix (trailing bits zero). Levels 1 handled by k_expm.
__global__ void __launch_bounds__(256) k_levels()
{
    extern __shared__ char smem[];
    uint32_t sb = smem_u32(smem);
    int s = blockIdx.x, h = blockIdx.y;
    int tid = threadIdx.x, wid = tid >> 5, lane = tid & 31;

    // stage P0 hi/lo, P1 hi/lo
    load_pad(sb + 0 * TILE_B, g_prod_h + (size_t)(0 * HEADS + h) * MSZ, tid, 256);
    load_pad(sb + 1 * TILE_B, g_prod_l + (size_t)(0 * HEADS + h) * MSZ, tid, 256);
    load_pad(sb + 2 * TILE_B, g_prod_h + (size_t)(1 * HEADS + h) * MSZ, tid, 256);
    load_pad(sb + 3 * TILE_B, g_prod_l + (size_t)(1 * HEADS + h) * MSZ, tid, 256);
    __syncthreads();

    int r0w = wid * 16;
    int t   = lane >> 3, r8 = lane & 7;
    int g   = lane >> 2, tig = lane & 3;
    uint32_t aOff = (uint32_t)((r0w + (t & 1) * 8 + r8) * RSB + (t >> 1) * 16);
    uint32_t bT   = (uint32_t)(((t & 1) * 8 + r8) * RSB + (t >> 1) * 16);

    // A-frags from P(root digit = bit 5)
    uint32_t Ah[8][4], Al[8][4];
    {
        uint32_t slot = sb + (uint32_t)(((s >> 5) & 1) * 2) * TILE_B;
#pragma unroll
        for (int kk = 0; kk < 8; kk++) {
            LDSM4(Ah[kk][0], Ah[kk][1], Ah[kk][2], Ah[kk][3], slot + aOff + kk * 32);
            LDSM4(Al[kk][0], Al[kk][1], Al[kk][2], Al[kk][3],
                  slot + TILE_B + aOff + kk * 32);
        }
    }

    float acc[16][4];
#pragma unroll
    for (int j = 1; j <= 5; j++) {
        int dj = (s >> (5 - j)) & 1;
        gemm3(acc, Ah, Al, sb + (uint32_t)(dj * 2) * TILE_B, bT);
        // canonical writer for prefix of length L=j+1 iff trailing bits zero
        if ((s & ((1 << (5 - j)) - 1)) == 0) {
            int b = s >> (5 - j);
            size_t pid = ((size_t)(((1 << (j + 1)) - 2 + b) * HEADS + h)) * MSZ;
            write_acc(acc, g_prod_f + pid, g_prod_h + pid, g_prod_l + pid,
                      r0w, g, tig);
        }
        if (j < 5) conv_frags(acc, Ah, Al);
    }
}

// ---------------- K4: chains, grid (NTOK, HEADS) ----------------
// depth<=6: copy f32 product. depth>=7: one GEMM prod(6,b1)@prod(d-6,b2).
__global__ void __launch_bounds__(256, 2) k_chain(float* __restrict__ out,
                                                  const int* __restrict__ positions)
{
    extern __shared__ char smem[];
    uint32_t sb = smem_u32(smem);
    int tid = threadIdx.x, wid = tid >> 5, lane = tid & 31;
    int n = blockIdx.x, h = blockIdx.y;
    float* outm = out + (size_t)(n * HEADS + h) * MSZ;

    // digits leaf->root packed: bit j = digit at distance j from leaf
    int Bbits = 0, depth = 0;
    for (int x = __ldg(positions + n); x > 0; x = (x - 1) >> 1)
        Bbits |= ((x - 1) & 1) << (depth++);

    if (depth == 0) {
        for (int e = tid; e < MSZ; e += 256)
            outm[e] = ((e >> 7) == (e & 127)) ? 1.0f : 0.0f;
        return;
    }
    if (depth <= 6) {
        int pid = (1 << depth) - 2 + Bbits;     // MSB-first == leaf->root pack
        const float4* src = (const float4*)(g_prod_f + ((size_t)(pid * HEADS + h)) * MSZ);
        float4* dst = (float4*)outm;
        for (int e = tid; e < MSZ / 4; e += 256) dst[e] = src[e];
        return;
    }

    int L2 = depth - 6;
    int b2 = Bbits & ((1 << L2) - 1);
    int b1 = Bbits >> L2;
    size_t p1 = ((size_t)((62 + b1) * HEADS + h)) * MSZ;                 // 2^6-2=62
    size_t p2 = ((size_t)(((1 << L2) - 2 + b2) * HEADS + h)) * MSZ;

    load_pad(sb,          g_prod_h + p2, tid, 256);
    load_pad(sb + TILE_B, g_prod_l + p2, tid, 256);
    __syncthreads();

    int r0w = wid * 16;
    int g = lane >> 2, tig = lane & 3;
    int t = lane >> 3, r8 = lane & 7;
    uint32_t bT = (uint32_t)(((t & 1) * 8 + r8) * RSB + (t >> 1) * 16);

    uint32_t Ah[8][4], Al[8][4];
    load_a_frags_g(g_prod_h + p1, g_prod_l + p1, Ah, Al, r0w, g, tig);

    float acc[16][4];
    gemm3(acc, Ah, Al, sb, bT);
    write_acc(acc, outm, nullptr, nullptr, r0w, g, tig);
}

// ---------------- host launcher ----------------
extern "C" void kernel_launch(void* const* d_in, const int* in_sizes, int n_in,
                              void* d_out, int out_size)
{
    const float* prim      = (const float*)d_in[0];
    const int*   positions = (const int*)d_in[1];
    float*       out       = (float*)d_out;
    (void)in_sizes; (void)n_in;

    cudaFuncSetAttribute(k_expm, cudaFuncAttributeMaxDynamicSharedMemorySize, SMEM_EXPM);
    cudaFuncSetAttribute(k_levels, cudaFuncAttributeMaxDynamicSharedMemorySize, SMEM_LVL);
    cudaFuncSetAttribute(k_chain, cudaFuncAttributeMaxDynamicSharedMemorySize, SMEM_GEMM);

    const int MAPS_ELEMS  = NTOK * HEADS * MSZ;
    const int STEPS_ELEMS = NTOK * NTOK;
    int write_steps = (out_size >= MAPS_ELEMS + STEPS_ELEMS) ? 1 : 0;
    float* steps_out = out + MAPS_ELEMS;

    if (write_steps) k_steps<<<NTOK, NTOK>>>(positions, steps_out);
    k_expm<<<NMAT, 256, SMEM_EXPM>>>(prim);
    {
        dim3 gl(64, HEADS);
        k_levels<<<gl, 256, SMEM_LVL>>>();
    }
    dim3 gc(NTOK, HEADS);
    k_chain<<<gc, 256, SMEM_GEMM>>>(out, positions);
}

// round 17
// speedup vs baseline: 1.1453x; 1.1453x over previous
#include <cuda_runtime.h>
#include <cuda_bf16.h>
#include <cstdint>

#define DIM   128
#define HEADS 8
#define MAXD  12
#define NTOK  256
#define MSZ   (DIM*DIM)      // 16384
#define NMAT  16             // sos (prims[-1]) unused by reference output
#define NPID  126            // prefix products of length 1..6: 2+4+...+64

// ---------------- device scratch ----------------
// prefix products indexed pid = 2^L - 2 + b (b = MSB-first digit string)
__device__ __align__(16) float         g_prod_f [NPID*HEADS*MSZ];   // 66 MB
__device__ __align__(16) __nv_bfloat16 g_prod_h [NPID*HEADS*MSZ];   // 33 MB
__device__ __align__(16) __nv_bfloat16 g_prod_l [NPID*HEADS*MSZ];   // 33 MB

// ---------------- helpers ----------------
__device__ __forceinline__ uint32_t smem_u32(const void* p) {
    uint32_t a;
    asm("{ .reg .u64 t; cvta.to.shared.u64 t, %1; cvt.u32.u64 %0, t; }" : "=r"(a) : "l"(p));
    return a;
}
#define STS128Q(a, r0, r1, r2, r3) \
    asm volatile("st.shared.v4.b32 [%0], {%1, %2, %3, %4};" \
                 :: "r"(a), "r"(r0), "r"(r1), "r"(r2), "r"(r3) : "memory")
#define STS32(a, v) \
    asm volatile("st.shared.b32 [%0], %1;" :: "r"(a), "r"(v) : "memory")
#define STS16(a, v) \
    asm volatile("st.shared.b16 [%0], %1;" :: "r"(a), "h"(v) : "memory")
#define LDS32(v, a) \
    asm volatile("ld.shared.b32 %0, [%1];" : "=r"(v) : "r"(a))
#define LDSM4(r0, r1, r2, r3, addr) \
    asm volatile("ldmatrix.sync.aligned.m8n8.x4.shared.b16 {%0, %1, %2, %3}, [%4];" \
                 : "=r"(r0), "=r"(r1), "=r"(r2), "=r"(r3) : "r"(addr))
#define LDSM4T(r0, r1, r2, r3, addr) \
    asm volatile("ldmatrix.sync.aligned.m8n8.x4.trans.shared.b16 {%0, %1, %2, %3}, [%4];" \
                 : "=r"(r0), "=r"(r1), "=r"(r2), "=r"(r3) : "r"(addr))
#define MMA16816(d, a, b0, b1) \
    asm volatile("mma.sync.aligned.m16n8k16.row.col.f32.bf16.bf16.f32 " \
                 "{%0, %1, %2, %3}, {%4, %5, %6, %7}, {%8, %9}, {%0, %1, %2, %3};" \
                 : "+f"((d)[0]), "+f"((d)[1]), "+f"((d)[2]), "+f"((d)[3]) \
                 : "r"((a)[0]), "r"((a)[1]), "r"((a)[2]), "r"((a)[3]), \
                   "r"(b0), "r"(b1))
__device__ __forceinline__ uint32_t pack_bf2(float flo, float fhi) {
    uint32_t r;
    asm("cvt.rn.bf16x2.f32 %0, %1, %2;" : "=r"(r) : "f"(fhi), "f"(flo));
    return r;
}

// padded rows: 136 bf16 = 272 B; tile = 128*272 B
#define RSB     272
#define TILE_B  34816
#define SMEM_EXPM (6*TILE_B)     // 208896 B
#define SMEM_LVL  (4*TILE_B)     // 139264 B (P0 hi/lo + P1 hi/lo)
#define SMEM_GEMM (2*TILE_B)     // 69632 B  (B tile hi/lo)

__device__ __forceinline__ void load_pad(uint32_t dst, const __nv_bfloat16* g,
                                         int t, int T) {
    const uint4* g4 = (const uint4*)g;
    for (int q = t; q < 2048; q += T) {
        uint4 v = g4[q];
        int r = q >> 4, c = (q & 15) << 3;
        STS128Q(dst + r * RSB + c * 2, v.x, v.y, v.z, v.w);
    }
}

// A fragments directly from global row-major bf16 (layout == LDSM4 delivery)
__device__ __forceinline__ void load_a_frags_g(
    const __nv_bfloat16* Ghi, const __nv_bfloat16* Glo,
    uint32_t Ah[8][4], uint32_t Al[8][4], int r0w, int g, int tig)
{
#pragma unroll
    for (int kk = 0; kk < 8; kk++) {
#pragma unroll
        for (int q = 0; q < 4; q++) {
            int row = r0w + g + ((q & 1) ? 8 : 0);
            int col = kk * 16 + tig * 2 + ((q & 2) ? 8 : 0);
            Ah[kk][q] = *(const uint32_t*)(Ghi + (size_t)row * DIM + col);
            Al[kk][q] = *(const uint32_t*)(Glo + (size_t)row * DIM + col);
        }
    }
}

// 3-pass bf16 HMMA: acc(16x[4]) = Arows(16) @ B(128x128); B row-major via
// ldmatrix.trans. bSlot = hi base; lo at +TILE_B.
__device__ __forceinline__ void gemm3(float acc[16][4],
                                      const uint32_t Ah[8][4],
                                      const uint32_t Al[8][4],
                                      uint32_t bSlot, uint32_t bT)
{
#pragma unroll
    for (int ni = 0; ni < 16; ni++)
#pragma unroll
        for (int q = 0; q < 4; q++) acc[ni][q] = 0.0f;
#pragma unroll
    for (int kk = 0; kk < 8; kk++) {
#pragma unroll
        for (int gq = 0; gq < 2; gq++) {
            uint32_t Bh[4][4], Bl[4][4];
#pragma unroll
            for (int j = 0; j < 4; j++) {
                uint32_t bA = bSlot + bT + (uint32_t)(kk * 16 * RSB)
                            + (uint32_t)((gq * 4 + j) * 32);
                LDSM4T(Bh[j][0], Bh[j][1], Bh[j][2], Bh[j][3], bA);
                LDSM4T(Bl[j][0], Bl[j][1], Bl[j][2], Bl[j][3], bA + TILE_B);
            }
#pragma unroll
            for (int j = 0; j < 4; j++) {
                int np = gq * 4 + j;
                MMA16816(acc[2*np],     Ah[kk], Bh[j][0], Bh[j][1]);
                MMA16816(acc[2*np + 1], Ah[kk], Bh[j][2], Bh[j][3]);
            }
#pragma unroll
            for (int j = 0; j < 4; j++) {
                int np = gq * 4 + j;
                MMA16816(acc[2*np],     Al[kk], Bh[j][0], Bh[j][1]);
                MMA16816(acc[2*np + 1], Al[kk], Bh[j][2], Bh[j][3]);
            }
#pragma unroll
            for (int j = 0; j < 4; j++) {
                int np = gq * 4 + j;
                MMA16816(acc[2*np],     Ah[kk], Bl[j][0], Bl[j][1]);
                MMA16816(acc[2*np + 1], Ah[kk], Bl[j][2], Bl[j][3]);
            }
        }
    }
}

__device__ __forceinline__ void conv_frags(const float acc[16][4],
                                           uint32_t Ah[8][4], uint32_t Al[8][4])
{
#pragma unroll
    for (int kk = 0; kk < 8; kk++) {
#pragma unroll
        for (int q = 0; q < 4; q++) {
            int nt = 2 * kk + (q >> 1);
            int bs = (q & 1) * 2;
            float v0 = acc[nt][bs], v1 = acc[nt][bs + 1];
            uint32_t hp = pack_bf2(v0, v1);
            float h0 = __uint_as_float(hp << 16);
            float h1 = __uint_as_float(hp & 0xffff0000u);
            Ah[kk][q] = hp;
            Al[kk][q] = pack_bf2(v0 - h0, v1 - h1);
        }
    }
}

// acc := cA*acc + cX*X + cI*I  (X from smem hi/lo)
__device__ __forceinline__ void epi_inplace(float acc[16][4],
    float cA, float cX, float cI, uint32_t xSlot, int r0w, int g, int tig)
{
    int r0 = r0w + g, r1 = r0w + g + 8;
#pragma unroll
    for (int ni = 0; ni < 16; ni++) {
        int col = ni * 8 + tig * 2;
        uint32_t a0 = xSlot + (uint32_t)(r0 * RSB + col * 2);
        uint32_t a1 = xSlot + (uint32_t)(r1 * RSB + col * 2);
        uint32_t h0, l0, h1, l1;
        LDS32(h0, a0); LDS32(l0, a0 + TILE_B);
        LDS32(h1, a1); LDS32(l1, a1 + TILE_B);
        float x00 = __uint_as_float(h0 << 16) + __uint_as_float(l0 << 16);
        float x01 = __uint_as_float(h0 & 0xffff0000u) + __uint_as_float(l0 & 0xffff0000u);
        float x10 = __uint_as_float(h1 << 16) + __uint_as_float(l1 << 16);
        float x11 = __uint_as_float(h1 & 0xffff0000u) + __uint_as_float(l1 & 0xffff0000u);
        acc[ni][0] = cA * acc[ni][0] + cX * x00 + ((r0 == col)     ? cI : 0.0f);
        acc[ni][1] = cA * acc[ni][1] + cX * x01 + ((r0 == col + 1) ? cI : 0.0f);
        acc[ni][2] = cA * acc[ni][2] + cX * x10 + ((r1 == col)     ? cI : 0.0f);
        acc[ni][3] = cA * acc[ni][3] + cX * x11 + ((r1 == col + 1) ? cI : 0.0f);
    }
}

__device__ __forceinline__ void store_buf(const float acc[16][4],
    uint32_t slot, int r0w, int g, int tig)
{
    int r0 = r0w + g, r1 = r0w + g + 8;
#pragma unroll
    for (int ni = 0; ni < 16; ni++) {
        int col = ni * 8 + tig * 2;
        float v0 = acc[ni][0], v1 = acc[ni][1];
        float v2 = acc[ni][2], v3 = acc[ni][3];
        uint32_t hp01 = pack_bf2(v0, v1), hp23 = pack_bf2(v2, v3);
        uint32_t lp01 = pack_bf2(v0 - __uint_as_float(hp01 << 16),
                                 v1 - __uint_as_float(hp01 & 0xffff0000u));
        uint32_t lp23 = pack_bf2(v2 - __uint_as_float(hp23 << 16),
                                 v3 - __uint_as_float(hp23 & 0xffff0000u));
        uint32_t a0 = slot + (uint32_t)(r0 * RSB + col * 2);
        uint32_t a1 = slot + (uint32_t)(r1 * RSB + col * 2);
        STS32(a0, hp01); STS32(a0 + TILE_B, lp01);
        STS32(a1, hp23); STS32(a1 + TILE_B, lp23);
    }
}

// write acc to f32 (optional) and bf16 hi/lo (optional) global row-major
__device__ __forceinline__ void write_acc(const float acc[16][4],
    float* outf, __nv_bfloat16* Gh, __nv_bfloat16* Gl, int r0w, int g, int tig)
{
    int r0 = r0w + g, r1 = r0w + g + 8;
#pragma unroll
    for (int ni = 0; ni < 16; ni++) {
        int col = ni * 8 + tig * 2;
        float v0 = acc[ni][0], v1 = acc[ni][1];
        float v2 = acc[ni][2], v3 = acc[ni][3];
        if (outf) {
            *(float2*)(outf + (size_t)r0 * DIM + col) = make_float2(v0, v1);
            *(float2*)(outf + (size_t)r1 * DIM + col) = make_float2(v2, v3);
        }
        if (Gh) {
            uint32_t hp01 = pack_bf2(v0, v1), hp23 = pack_bf2(v2, v3);
            uint32_t lp01 = pack_bf2(v0 - __uint_as_float(hp01 << 16),
                                     v1 - __uint_as_float(hp01 & 0xffff0000u));
            uint32_t lp23 = pack_bf2(v2 - __uint_as_float(hp23 << 16),
                                     v3 - __uint_as_float(hp23 & 0xffff0000u));
            *(uint32_t*)(Gh + (size_t)r0 * DIM + col) = hp01;
            *(uint32_t*)(Gh + (size_t)r1 * DIM + col) = hp23;
            *(uint32_t*)(Gl + (size_t)r0 * DIM + col) = lp01;
            *(uint32_t*)(Gl + (size_t)r1 * DIM + col) = lp23;
        }
    }
}

// ---------------- K1: steps via LCA, grid (256, 256 thr) ----------------
__global__ void k_steps(const int* __restrict__ positions,
                        float* __restrict__ steps_out)
{
    int i = blockIdx.x, j = threadIdx.x;
    int u = __ldg(positions + i), w = __ldg(positions + j);
    int du = 0, dw = 0;
    for (int x = u; x > 0; x = (x - 1) >> 1) du++;
    for (int x = w; x > 0; x = (x - 1) >> 1) dw++;
    int su = u, sw = w, a = du, b = dw;
    while (a > b) { su = (su - 1) >> 1; a--; }
    while (b > a) { sw = (sw - 1) >> 1; b--; }
    while (su != sw) { su = (su - 1) >> 1; sw = (sw - 1) >> 1; a--; }
    steps_out[i * NTOK + j] = (float)(du + dw - 2 * a);
}

// ---------------- K2: fused expm (one CTA per matrix) ----------------
// Writes pid 0/1 (length-1 products): offsets (digit*8+h)*MSZ == m*MSZ.
__global__ void __launch_bounds__(256) k_expm(const float* __restrict__ prim)
{
    extern __shared__ char smem[];
    uint32_t sb = smem_u32(smem);
    int tid = threadIdx.x, wid = tid >> 5, lane = tid & 31;
    int m = blockIdx.x;
    const float* A = prim + (size_t)m * MSZ;

    for (int e = tid; e < MSZ; e += 256) {
        int i = e >> 7, j = e & 127;
        float x = (A[e] - A[j * DIM + i]) * (1.0f / 16.0f);
        __nv_bfloat16 hb = __float2bfloat16(x);
        float hf = __bfloat162float(hb);
        __nv_bfloat16 lb = __float2bfloat16(x - hf);
        uint32_t ad = sb + (uint32_t)(i * RSB + j * 2);
        STS16(ad, (unsigned short)__bfloat16_as_ushort(hb));
        STS16(ad + TILE_B, (unsigned short)__bfloat16_as_ushort(lb));
    }
    __syncthreads();

    int r0w = wid * 16;
    int t   = lane >> 3, r8 = lane & 7;
    int g   = lane >> 2, tig = lane & 3;
    uint32_t aOff = (uint32_t)((r0w + (t & 1) * 8 + r8) * RSB + (t >> 1) * 16);
    uint32_t bT   = (uint32_t)(((t & 1) * 8 + r8) * RSB + (t >> 1) * 16);
    uint32_t slotX  = sb + 0 * TILE_B;
    uint32_t slotB0 = sb + 2 * TILE_B;
    uint32_t slotB1 = sb + 4 * TILE_B;

    const float c2 = 1.0f/2.0f, c3 = 1.0f/6.0f, c4 = 1.0f/24.0f, c5 = 1.0f/120.0f;
    const float c6 = 1.0f/720.0f, c7 = 1.0f/5040.0f, c8 = 1.0f/40320.0f;

    uint32_t Xa[8][4], Xal[8][4];
#pragma unroll
    for (int kk = 0; kk < 8; kk++) {
        LDSM4(Xa[kk][0], Xa[kk][1], Xa[kk][2], Xa[kk][3], slotX + aOff + kk * 32);
        LDSM4(Xal[kk][0], Xal[kk][1], Xal[kk][2], Xal[kk][3],
              slotX + TILE_B + aOff + kk * 32);
    }

    float acc[16][4];
    uint32_t X2h[8][4], X2l[8][4];

    gemm3(acc, Xa, Xal, slotX, bT);
    conv_frags(acc, X2h, X2l);
    epi_inplace(acc, c8, c7, c6, slotX, r0w, g, tig);
    store_buf(acc, slotB0, r0w, g, tig);
    __syncthreads();
    gemm3(acc, X2h, X2l, slotB0, bT);
    epi_inplace(acc, 1.0f, c5, c4, slotX, r0w, g, tig);
    store_buf(acc, slotB1, r0w, g, tig);
    __syncthreads();
    gemm3(acc, X2h, X2l, slotB1, bT);
    epi_inplace(acc, 1.0f, c3, c2, slotX, r0w, g, tig);
    store_buf(acc, slotB0, r0w, g, tig);
    __syncthreads();
    gemm3(acc, X2h, X2l, slotB0, bT);
    epi_inplace(acc, 1.0f, 1.0f, 1.0f, slotX, r0w, g, tig);
    store_buf(acc, slotB1, r0w, g, tig);
    uint32_t Sh[8][4], Sl[8][4];
    conv_frags(acc, Sh, Sl);
    __syncthreads();

#pragma unroll
    for (int q = 0; q < 4; q++) {
        uint32_t rd = (q & 1) ? slotB0 : slotB1;
        uint32_t wr = (q & 1) ? slotB1 : slotB0;
        gemm3(acc, Sh, Sl, rd, bT);
        conv_frags(acc, Sh, Sl);
        if (q < 3) {
            store_buf(acc, wr, r0w, g, tig);
            __syncthreads();
        }
    }

    write_acc(acc, g_prod_f + (size_t)m * MSZ,
              g_prod_h + (size_t)m * MSZ, g_prod_l + (size_t)m * MSZ,
              r0w, g, tig);
}

// ---------------- K3a: lengths 2 & 3 via 3-bit chains ----------------
// grid (8, HEADS): CTA s register-chains P(s2)@P(s1)@P(s0); writes L2 when
// canonical (s&1==0) and L3 always. 16 GEMMs/head.
__global__ void __launch_bounds__(256) k_lvl3()
{
    extern __shared__ char smem[];
    uint32_t sb = smem_u32(smem);
    int s = blockIdx.x, h = blockIdx.y;
    int tid = threadIdx.x, wid = tid >> 5, lane = tid & 31;

    load_pad(sb + 0 * TILE_B, g_prod_h + (size_t)(0 * HEADS + h) * MSZ, tid, 256);
    load_pad(sb + 1 * TILE_B, g_prod_l + (size_t)(0 * HEADS + h) * MSZ, tid, 256);
    load_pad(sb + 2 * TILE_B, g_prod_h + (size_t)(1 * HEADS + h) * MSZ, tid, 256);
    load_pad(sb + 3 * TILE_B, g_prod_l + (size_t)(1 * HEADS + h) * MSZ, tid, 256);
    __syncthreads();

    int r0w = wid * 16;
    int t   = lane >> 3, r8 = lane & 7;
    int g   = lane >> 2, tig = lane & 3;
    uint32_t aOff = (uint32_t)((r0w + (t & 1) * 8 + r8) * RSB + (t >> 1) * 16);
    uint32_t bT   = (uint32_t)(((t & 1) * 8 + r8) * RSB + (t >> 1) * 16);

    // A-frags from P(root digit = bit 2)
    uint32_t Ah[8][4], Al[8][4];
    {
        uint32_t slot = sb + (uint32_t)(((s >> 2) & 1) * 2) * TILE_B;
#pragma unroll
        for (int kk = 0; kk < 8; kk++) {
            LDSM4(Ah[kk][0], Ah[kk][1], Ah[kk][2], Ah[kk][3], slot + aOff + kk * 32);
            LDSM4(Al[kk][0], Al[kk][1], Al[kk][2], Al[kk][3],
                  slot + TILE_B + aOff + kk * 32);
        }
    }

    float acc[16][4];
    // L2 = P(bit2) @ P(bit1)
    gemm3(acc, Ah, Al, sb + (uint32_t)(((s >> 1) & 1) * 2) * TILE_B, bT);
    if ((s & 1) == 0) {
        size_t pid = ((size_t)((2 + (s >> 1)) * HEADS + h)) * MSZ;
        write_acc(acc, g_prod_f + pid, g_prod_h + pid, g_prod_l + pid,
                  r0w, g, tig);
    }
    conv_frags(acc, Ah, Al);
    // L3 = L2 @ P(bit0)
    gemm3(acc, Ah, Al, sb + (uint32_t)((s & 1) * 2) * TILE_B, bT);
    {
        size_t pid = ((size_t)((6 + s) * HEADS + h)) * MSZ;
        write_acc(acc, g_prod_f + pid, g_prod_h + pid, g_prod_l + pid,
                  r0w, g, tig);
    }
}

// ---------------- K3b: lengths 4,5,6 = prod(3,hi) @ prod(L-3,lo) ----------
// grid (112, HEADS): i<16 -> L4, i<48 -> L5, else L6. One GEMM each.
__global__ void __launch_bounds__(256, 2) k_lvl456()
{
    extern __shared__ char smem[];
    uint32_t sb = smem_u32(smem);
    int i = blockIdx.x, h = blockIdx.y;
    int tid = threadIdx.x, wid = tid >> 5, lane = tid & 31;

    int L, b;
    if (i < 16)      { L = 4; b = i; }
    else if (i < 48) { L = 5; b = i - 16; }
    else             { L = 6; b = i - 48; }
    int Lo = L - 3;
    int hi = b >> Lo;
    int lo = b & ((1 << Lo) - 1);
    size_t p1 = ((size_t)((6 + hi) * HEADS + h)) * MSZ;                // pid(3,hi)
    size_t p2 = ((size_t)(((1 << Lo) - 2 + lo) * HEADS + h)) * MSZ;    // pid(Lo,lo)
    size_t po = ((size_t)(((1 << L) - 2 + b) * HEADS + h)) * MSZ;      // pid(L,b)

    int r0w = wid * 16;
    int g = lane >> 2, tig = lane & 3;
    int t = lane >> 3, r8 = lane & 7;
    uint32_t bT = (uint32_t)(((t & 1) * 8 + r8) * RSB + (t >> 1) * 16);

    uint32_t Ah[8][4], Al[8][4];
    load_a_frags_g(g_prod_h + p1, g_prod_l + p1, Ah, Al, r0w, g, tig);

    load_pad(sb,          g_prod_h + p2, tid, 256);
    load_pad(sb + TILE_B, g_prod_l + p2, tid, 256);
    __syncthreads();

    float acc[16][4];
    gemm3(acc, Ah, Al, sb, bT);
    write_acc(acc, g_prod_f + po, g_prod_h + po, g_prod_l + po, r0w, g, tig);
}

// ---------------- K4: chains, grid (NTOK, HEADS) ----------------
// depth<=6: copy f32 product. depth>=7: one GEMM prod(6,b1)@prod(d-6,b2).
__global__ void __launch_bounds__(256, 2) k_chain(float* __restrict__ out,
                                                  const int* __restrict__ positions)
{
    extern __shared__ char smem[];
    uint32_t sb = smem_u32(smem);
    int tid = threadIdx.x, wid = tid >> 5, lane = tid & 31;
    int n = blockIdx.x, h = blockIdx.y;
    float* outm = out + (size_t)(n * HEADS + h) * MSZ;

    // digits leaf->root packed: bit j = digit at distance j from leaf
    int Bbits = 0, depth = 0;
    for (int x = __ldg(positions + n); x > 0; x = (x - 1) >> 1)
        Bbits |= ((x - 1) & 1) << (depth++);

    if (depth == 0) {
        for (int e = tid; e < MSZ; e += 256)
            outm[e] = ((e >> 7) == (e & 127)) ? 1.0f : 0.0f;
        return;
    }
    if (depth <= 6) {
        int pid = (1 << depth) - 2 + Bbits;     // MSB-first == leaf->root pack
        const float4* src = (const float4*)(g_prod_f + ((size_t)(pid * HEADS + h)) * MSZ);
        float4* dst = (float4*)outm;
        for (int e = tid; e < MSZ / 4; e += 256) dst[e] = src[e];
        return;
    }

    int L2 = depth - 6;
    int b2 = Bbits & ((1 << L2) - 1);
    int b1 = Bbits >> L2;
    size_t p1 = ((size_t)((62 + b1) * HEADS + h)) * MSZ;                 // 2^6-2=62
    size_t p2 = ((size_t)(((1 << L2) - 2 + b2) * HEADS + h)) * MSZ;

    int r0w = wid * 16;
    int g = lane >> 2, tig = lane & 3;
    int t = lane >> 3, r8 = lane & 7;
    uint32_t bT = (uint32_t)(((t & 1) * 8 + r8) * RSB + (t >> 1) * 16);

    // issue A-fragment loads first so they overlap the B staging
    uint32_t Ah[8][4], Al[8][4];
    load_a_frags_g(g_prod_h + p1, g_prod_l + p1, Ah, Al, r0w, g, tig);

    load_pad(sb,          g_prod_h + p2, tid, 256);
    load_pad(sb + TILE_B, g_prod_l + p2, tid, 256);
    __syncthreads();

    float acc[16][4];
    gemm3(acc, Ah, Al, sb, bT);
    write_acc(acc, outm, nullptr, nullptr, r0w, g, tig);
}

// ---------------- host launcher ----------------
extern "C" void kernel_launch(void* const* d_in, const int* in_sizes, int n_in,
                              void* d_out, int out_size)
{
    const float* prim      = (const float*)d_in[0];
    const int*   positions = (const int*)d_in[1];
    float*       out       = (float*)d_out;
    (void)in_sizes; (void)n_in;

    cudaFuncSetAttribute(k_expm, cudaFuncAttributeMaxDynamicSharedMemorySize, SMEM_EXPM);
    cudaFuncSetAttribute(k_lvl3, cudaFuncAttributeMaxDynamicSharedMemorySize, SMEM_LVL);
    cudaFuncSetAttribute(k_lvl456, cudaFuncAttributeMaxDynamicSharedMemorySize, SMEM_GEMM);
    cudaFuncSetAttribute(k_chain, cudaFuncAttributeMaxDynamicSharedMemorySize, SMEM_GEMM);

    const int MAPS_ELEMS  = NTOK * HEADS * MSZ;
    const int STEPS_ELEMS = NTOK * NTOK;
    int write_steps = (out_size >= MAPS_ELEMS + STEPS_ELEMS) ? 1 : 0;
    float* steps_out = out + MAPS_ELEMS;

    if (write_steps) k_steps<<<NTOK, NTOK>>>(positions, steps_out);
    k_expm<<<NMAT, 256, SMEM_EXPM>>>(prim);
    {
        dim3 g3(8, HEADS);
        k_lvl3<<<g3, 256, SMEM_LVL>>>();
    }
    {
        dim3 g456(112, HEADS);
        k_lvl456<<<g456, 256, SMEM_GEMM>>>();
    }
    dim3 gc(NTOK, HEADS);
    k_chain<<<gc, 256, SMEM_GEMM>>>(out, positions);
}